// round 1
// baseline (speedup 1.0000x reference)
#include <cuda_runtime.h>
#include <math.h>

#define B      8192
#define D      512
#define ALPHA  0.5f
#define MARGIN 0.5f
#define TILE   128
#define NT     (B / TILE)   // 64
#define TK     16
#define BCE_BLOCKS 32

// Scratch (no cudaMalloc allowed)
__device__ float g_e[B * D];        // normalized embeddings (16 MB)
__device__ float g_sq[B];           // row squared norms of e (~1.0)
__device__ float g_part[NT * NT];   // per-tile partial pair sums
__device__ float g_bce[BCE_BLOCKS]; // BCE partials

// ---------------------------------------------------------------------------
// Kernel 1: row-wise L2 normalize, emit e and sq = ||e||^2
// one block per row, 128 threads, one float4 per thread (D=512)
// ---------------------------------------------------------------------------
__global__ void normalize_kernel(const float* __restrict__ emb) {
    int row = blockIdx.x;
    int t = threadIdx.x;  // 0..127
    float4 v = ((const float4*)(emb + row * D))[t];
    float s = v.x * v.x + v.y * v.y + v.z * v.z + v.w * v.w;
    #pragma unroll
    for (int o = 16; o > 0; o >>= 1) s += __shfl_down_sync(0xffffffff, s, o);
    __shared__ float sm[4];
    if ((t & 31) == 0) sm[t >> 5] = s;
    __syncthreads();
    float tot = sm[0] + sm[1] + sm[2] + sm[3];
    float inv = 1.0f / fmaxf(sqrtf(tot), 1e-12f);
    float4 o4 = make_float4(v.x * inv, v.y * inv, v.z * inv, v.w * inv);
    ((float4*)(g_e + row * D))[t] = o4;
    if (t == 0) g_sq[row] = tot * inv * inv;
}

// ---------------------------------------------------------------------------
// Kernel 2: tiled Gram + fused mask epilogue.
// Grid (NT, NT); block (ti=blockIdx.y, tj=blockIdx.x) active iff tj >= ti.
// 256 threads, 8x8 micro-tile per thread, K-chunks of 16 in shared memory.
// ---------------------------------------------------------------------------
__global__ void __launch_bounds__(256)
pair_kernel(const float* __restrict__ classes, const int* __restrict__ ids) {
    const int ti = blockIdx.y, tj = blockIdx.x;
    const int pidx = ti * NT + tj;
    if (tj < ti) {  // lower triangle: no work
        if (threadIdx.x == 0) g_part[pidx] = 0.0f;
        return;
    }

    __shared__ float As[TK][TILE];
    __shared__ float Bs[TK][TILE];
    __shared__ int   idsI[TILE], idsJ[TILE];
    __shared__ float clsI[TILE], clsJ[TILE], sqI[TILE], sqJ[TILE];

    const int tid = threadIdx.x;       // 0..255
    const int tx = tid & 15;           // 0..15 (j micro-col)
    const int ty = tid >> 4;           // 0..15 (i micro-row)
    const int iBase = ti * TILE, jBase = tj * TILE;

    if (tid < TILE) {
        idsI[tid] = ids[iBase + tid];
        clsI[tid] = classes[iBase + tid];
        sqI[tid]  = g_sq[iBase + tid];
    } else {
        int r = tid - TILE;
        idsJ[r] = ids[jBase + r];
        clsJ[r] = classes[jBase + r];
        sqJ[r]  = g_sq[jBase + r];
    }

    float c[8][8];
    #pragma unroll
    for (int m = 0; m < 8; m++)
        #pragma unroll
        for (int n = 0; n < 8; n++) c[m][n] = 0.0f;

    const float* Ag = g_e + (size_t)iBase * D;
    const float* Bg = g_e + (size_t)jBase * D;

    for (int kb = 0; kb < D; kb += TK) {
        // Load 128 rows x 16 k per tile = 512 float4s; 2 per thread.
        #pragma unroll
        for (int l = 0; l < 2; l++) {
            int f = tid + l * 256;     // 0..511
            int r = f >> 2;            // row in tile
            int q = f & 3;             // which float4 within the 16-k chunk
            float4 va = *(const float4*)(Ag + r * D + kb + q * 4);
            As[q * 4 + 0][r] = va.x; As[q * 4 + 1][r] = va.y;
            As[q * 4 + 2][r] = va.z; As[q * 4 + 3][r] = va.w;
            float4 vb = *(const float4*)(Bg + r * D + kb + q * 4);
            Bs[q * 4 + 0][r] = vb.x; Bs[q * 4 + 1][r] = vb.y;
            Bs[q * 4 + 2][r] = vb.z; Bs[q * 4 + 3][r] = vb.w;
        }
        __syncthreads();

        #pragma unroll
        for (int k = 0; k < TK; k++) {
            float4 a0 = *(const float4*)&As[k][ty * 8];
            float4 a1 = *(const float4*)&As[k][ty * 8 + 4];
            float4 b0 = *(const float4*)&Bs[k][tx * 8];
            float4 b1 = *(const float4*)&Bs[k][tx * 8 + 4];
            float a[8] = {a0.x, a0.y, a0.z, a0.w, a1.x, a1.y, a1.z, a1.w};
            float b[8] = {b0.x, b0.y, b0.z, b0.w, b1.x, b1.y, b1.z, b1.w};
            #pragma unroll
            for (int m = 0; m < 8; m++)
                #pragma unroll
                for (int n = 0; n < 8; n++)
                    c[m][n] = fmaf(a[m], b[n], c[m][n]);
        }
        __syncthreads();
    }

    // Fused epilogue: masks + hinge, upper-triangle only on diagonal tiles.
    const bool diag = (ti == tj);
    float local = 0.0f;
    #pragma unroll
    for (int m = 0; m < 8; m++) {
        int ri = ty * 8 + m;
        int   id_i = idsI[ri];
        float cl_i = clsI[ri];
        float sq_i = sqI[ri];
        #pragma unroll
        for (int n = 0; n < 8; n++) {
            int rj = tx * 8 + n;
            if (diag && rj <= ri) continue;
            float d2 = fmaxf(sq_i + sqJ[rj] - 2.0f * c[m][n], 0.0f);
            bool same_id = (id_i == idsJ[rj]);
            bool same_cl = (cl_i == clsJ[rj]);
            float term = 0.0f;
            if (same_id && !same_cl)       term = 0.5f * d2;
            else if (!same_id && same_cl)  term = fmaxf(0.0f, MARGIN - d2);
            local += term;
        }
    }

    __shared__ float red[256];
    red[tid] = local;
    __syncthreads();
    #pragma unroll
    for (int s = 128; s > 0; s >>= 1) {
        if (tid < s) red[tid] += red[tid + s];
        __syncthreads();
    }
    if (tid == 0) g_part[pidx] = red[0];
}

// ---------------------------------------------------------------------------
// Kernel 3: BCE partials (numerically stable, matches reference)
// ---------------------------------------------------------------------------
__global__ void bce_kernel(const float* __restrict__ outputs,
                           const float* __restrict__ classes) {
    float s = 0.0f;
    for (int i = blockIdx.x * blockDim.x + threadIdx.x; i < B;
         i += gridDim.x * blockDim.x) {
        float o = outputs[i], cl = classes[i];
        s += fmaxf(o, 0.0f) - o * cl + log1pf(expf(-fabsf(o)));
    }
    __shared__ float red[256];
    red[threadIdx.x] = s;
    __syncthreads();
    #pragma unroll
    for (int k = 128; k > 0; k >>= 1) {
        if (threadIdx.x < k) red[threadIdx.x] += red[threadIdx.x + k];
        __syncthreads();
    }
    if (threadIdx.x == 0) g_bce[blockIdx.x] = red[0];
}

// ---------------------------------------------------------------------------
// Kernel 4: deterministic final reduce -> scalar output
// ---------------------------------------------------------------------------
__global__ void final_kernel(float* __restrict__ out) {
    int t = threadIdx.x;  // 256
    float s = 0.0f;
    for (int i = t; i < NT * NT; i += 256) s += g_part[i];
    __shared__ float red[256];
    red[t] = s;
    __syncthreads();
    #pragma unroll
    for (int k = 128; k > 0; k >>= 1) {
        if (t < k) red[t] += red[t + k];
        __syncthreads();
    }
    if (t == 0) {
        float bsum = 0.0f;
        #pragma unroll
        for (int i = 0; i < BCE_BLOCKS; i++) bsum += g_bce[i];
        out[0] = bsum / (float)B + ALPHA * red[0];
    }
}

// ---------------------------------------------------------------------------
extern "C" void kernel_launch(void* const* d_in, const int* in_sizes, int n_in,
                              void* d_out, int out_size) {
    const float* outputs = (const float*)d_in[0];
    const float* classes = (const float*)d_in[1];
    const float* emb     = (const float*)d_in[2];
    const int*   ids     = (const int*)d_in[3];
    float* out = (float*)d_out;

    normalize_kernel<<<B, 128>>>(emb);
    pair_kernel<<<dim3(NT, NT), 256>>>(classes, ids);
    bce_kernel<<<BCE_BLOCKS, 256>>>(outputs, classes);
    final_kernel<<<1, 256>>>(out);
}

// round 2
// speedup vs baseline: 4.6789x; 4.6789x over previous
#include <cuda_runtime.h>
#include <cuda_bf16.h>
#include <math.h>
#include <stdint.h>

#define B      8192
#define D      512
#define ALPHA  0.5f
#define MARGIN 0.5f
#define NUM_IDS 1024
#define NT     (B / 128)     // 64 tiles per dim
#define BCE_BLOCKS 32
#define CAP    (1u << 20)    // candidate buffer capacity
#define MAXG   128           // max rows per id group

// ---------------- scratch (no cudaMalloc allowed) ----------------
__device__ float          g_e[B * D];      // normalized embeddings fp32 (16 MB)
__device__ __nv_bfloat16  g_ebf[B * D];    // bf16 copy (8 MB)
__device__ float          g_sq[B];         // ||e||^2 per row (~1.0)
__device__ float          g_pull[NUM_IDS]; // per-id pull partial
__device__ float          g_bce[BCE_BLOCKS];
__device__ unsigned       g_cand[CAP];     // flagged pairs (i<<13 | j)
__device__ unsigned       g_cand_n;
__device__ float          g_hinge;         // exact hinge sum (fixup)

// ---------------- PTX helpers ----------------
__device__ __forceinline__ void cpa16(uint32_t dst, const void* src) {
    asm volatile("cp.async.cg.shared.global [%0], [%1], 16;\n" :: "r"(dst), "l"(src));
}
#define CP_COMMIT() asm volatile("cp.async.commit_group;\n" ::: "memory")
#define CP_WAIT1()  asm volatile("cp.async.wait_group 1;\n" ::: "memory")

__device__ __forceinline__ void ldsm4(uint32_t* r, uint32_t addr) {
    asm volatile("ldmatrix.sync.aligned.m8n8.x4.shared.b16 {%0,%1,%2,%3}, [%4];\n"
                 : "=r"(r[0]), "=r"(r[1]), "=r"(r[2]), "=r"(r[3]) : "r"(addr));
}
__device__ __forceinline__ void mma16816(float* d, const uint32_t* a,
                                         uint32_t b0, uint32_t b1) {
    asm volatile(
        "mma.sync.aligned.m16n8k16.row.col.f32.bf16.bf16.f32 "
        "{%0,%1,%2,%3}, {%4,%5,%6,%7}, {%8,%9}, {%0,%1,%2,%3};\n"
        : "+f"(d[0]), "+f"(d[1]), "+f"(d[2]), "+f"(d[3])
        : "r"(a[0]), "r"(a[1]), "r"(a[2]), "r"(a[3]), "r"(b0), "r"(b1));
}

// ---------------- kernel 0: reset accumulators ----------------
__global__ void init_kernel() {
    g_cand_n = 0u;
    g_hinge = 0.0f;
}

// ---------------- kernel 1: normalize -> g_e (fp32), g_ebf (bf16), g_sq -----
__global__ void normalize_kernel(const float* __restrict__ emb) {
    int row = blockIdx.x;
    int t = threadIdx.x;  // 0..127
    float4 v = ((const float4*)(emb + (size_t)row * D))[t];
    float s = v.x * v.x + v.y * v.y + v.z * v.z + v.w * v.w;
    #pragma unroll
    for (int o = 16; o > 0; o >>= 1) s += __shfl_down_sync(0xffffffff, s, o);
    __shared__ float sm[4];
    if ((t & 31) == 0) sm[t >> 5] = s;
    __syncthreads();
    float tot = sm[0] + sm[1] + sm[2] + sm[3];
    float inv = 1.0f / fmaxf(sqrtf(tot), 1e-12f);
    float4 o4 = make_float4(v.x * inv, v.y * inv, v.z * inv, v.w * inv);
    ((float4*)(g_e + (size_t)row * D))[t] = o4;
    __nv_bfloat162 p0 = __floats2bfloat162_rn(o4.x, o4.y);
    __nv_bfloat162 p1 = __floats2bfloat162_rn(o4.z, o4.w);
    uint2 u;
    u.x = *(uint32_t*)&p0;
    u.y = *(uint32_t*)&p1;
    ((uint2*)(g_ebf + (size_t)row * D))[t] = u;
    if (t == 0) g_sq[row] = tot * inv * inv;
}

// ---------------- kernel 2: exact pull term per id (grouping trick) --------
// P_id = sum_{i in (g,c0), j in (g,c1)} (sq_i + sq_j - 2 e_i.e_j)
//      = n1*sqsum0 + n0*sqsum1 - 2 * S0.S1
__global__ void __launch_bounds__(256) pull_kernel(const float* __restrict__ classes,
                                                   const int* __restrict__ ids) {
    int g = blockIdx.x;
    int t = threadIdx.x;
    __shared__ unsigned mask[256];
    __shared__ int   list[MAXG];
    __shared__ float lcls[MAXG];
    __shared__ int   cnt_s;
    __shared__ float n0s, n1s, sq0s, sq1s;
    __shared__ float red[256];

    mask[t] = 0u;
    __syncthreads();
    #pragma unroll
    for (int it = 0; it < B / 256; it++) {
        int r = t + it * 256;
        if (ids[r] == g) atomicOr(&mask[r >> 5], 1u << (r & 31));
    }
    __syncthreads();
    if (t == 0) {
        int c = 0;
        float n0 = 0.f, n1 = 0.f, s0 = 0.f, s1 = 0.f;
        for (int w = 0; w < 256; w++) {
            unsigned m = mask[w];
            while (m) {
                int b = __ffs(m) - 1;
                m &= m - 1;
                int r = w * 32 + b;
                float cl = classes[r];
                float sq = g_sq[r];
                if (c < MAXG) { list[c] = r; lcls[c] = cl; }
                c++;
                if (cl == 0.0f) { n0 += 1.f; s0 += sq; }
                else            { n1 += 1.f; s1 += sq; }
            }
        }
        cnt_s = c; n0s = n0; n1s = n1; sq0s = s0; sq1s = s1;
    }
    __syncthreads();
    int cnt = cnt_s < MAXG ? cnt_s : MAXG;
    // each thread owns dims t and t+256
    float a0 = 0.f, a1 = 0.f, b0 = 0.f, b1 = 0.f;
    for (int k = 0; k < cnt; k++) {
        int r = list[k];
        float cl = lcls[k];
        float v0 = g_e[(size_t)r * D + t];
        float v1 = g_e[(size_t)r * D + t + 256];
        if (cl == 0.0f) { a0 += v0; b0 += v1; }
        else            { a1 += v0; b1 += v1; }
    }
    red[t] = a0 * a1 + b0 * b1;
    __syncthreads();
    #pragma unroll
    for (int s = 128; s > 0; s >>= 1) {
        if (t < s) red[t] += red[t + s];
        __syncthreads();
    }
    if (t == 0)
        g_pull[g] = n1s * sq0s + n0s * sq1s - 2.0f * red[0];
}

// ---------------- kernel 3: bf16 Gram + hinge-candidate detection ----------
// Block tile 128x128, upper triangle only. 8 warps, warp tile 32x64.
// smem layout per stage: 128 rows x 64B (BK=32 bf16), XOR swizzle on 16B groups:
//   off(row, grp) = row*64 + ((grp ^ ((row>>1)&3)) << 4)
__global__ void __launch_bounds__(256) gram_kernel() {
    const int ti = blockIdx.y, tj = blockIdx.x;
    if (tj < ti) return;

    __shared__ __align__(1024) unsigned char smem[4 * 8192];  // A0 A1 B0 B1
    __shared__ float sqI[128], sqJ[128];

    const int tid = threadIdx.x;
    const int lane = tid & 31, warp = tid >> 5;
    const int wy = warp >> 1, wx = warp & 1;   // warp tile: M = wy*32, N = wx*64
    const int iBase = ti * 128, jBase = tj * 128;

    if (tid < 128) sqI[tid] = g_sq[iBase + tid];
    else           sqJ[tid - 128] = g_sq[jBase + tid - 128];

    const uint32_t sBase = (uint32_t)__cvta_generic_to_shared(smem);

    float acc[2][8][4];
    #pragma unroll
    for (int m = 0; m < 2; m++)
        #pragma unroll
        for (int n = 0; n < 8; n++)
            #pragma unroll
            for (int r = 0; r < 4; r++) acc[m][n][r] = 0.0f;

    // per-thread cp.async coordinates: row = tid>>1, two 16B groups q0,q0+1
    const int ldr = tid >> 1;
    const int q0 = (tid & 1) << 1;
    const int sw = (ldr >> 1) & 3;
    const uint32_t dA0 = ldr * 64 + (((q0)     ^ sw) << 4);
    const uint32_t dA1 = ldr * 64 + (((q0 + 1) ^ sw) << 4);

    auto loadStage = [&](int kb, int buf) {
        const __nv_bfloat16* pa = g_ebf + (size_t)(iBase + ldr) * D + kb + q0 * 8;
        const __nv_bfloat16* pb = g_ebf + (size_t)(jBase + ldr) * D + kb + q0 * 8;
        uint32_t a_off = sBase + buf * 8192;
        uint32_t b_off = sBase + 16384 + buf * 8192;
        cpa16(a_off + dA0, pa);
        cpa16(a_off + dA1, pa + 8);
        cpa16(b_off + dA0, pb);
        cpa16(b_off + dA1, pb + 8);
    };

    loadStage(0, 0);
    CP_COMMIT();

    const int lrow = lane & 7;
    const int subh = (lane >> 3) & 1;
    const int subg = lane >> 4;

    #pragma unroll 1
    for (int s = 0; s < D / 32; s++) {
        if (s + 1 < D / 32) loadStage((s + 1) * 32, (s + 1) & 1);
        CP_COMMIT();
        CP_WAIT1();
        __syncthreads();

        const int buf = s & 1;
        const uint32_t baseA = sBase + buf * 8192;
        const uint32_t baseB = sBase + 16384 + buf * 8192;

        #pragma unroll
        for (int ks = 0; ks < 2; ks++) {
            uint32_t a[2][4];
            #pragma unroll
            for (int ma = 0; ma < 2; ma++) {
                int row = wy * 32 + ma * 16 + lrow + subh * 8;
                int grp = 2 * ks + subg;
                uint32_t ad = baseA + row * 64 + ((grp ^ ((row >> 1) & 3)) << 4);
                ldsm4(a[ma], ad);
            }
            uint32_t bfr[4][4];
            #pragma unroll
            for (int nb = 0; nb < 4; nb++) {
                int row = wx * 64 + nb * 16 + lrow + subh * 8;
                int grp = 2 * ks + subg;
                uint32_t ad = baseB + row * 64 + ((grp ^ ((row >> 1) & 3)) << 4);
                ldsm4(bfr[nb], ad);
            }
            #pragma unroll
            for (int ma = 0; ma < 2; ma++)
                #pragma unroll
                for (int nb = 0; nb < 4; nb++) {
                    mma16816(acc[ma][2 * nb],     a[ma], bfr[nb][0], bfr[nb][2]);
                    mma16816(acc[ma][2 * nb + 1], a[ma], bfr[nb][1], bfr[nb][3]);
                }
        }
        __syncthreads();
    }

    // epilogue: flag dot > 0.5*(sq_i+sq_j) - 0.2551  (covers hinge boundary
    // 0.5*(sq_i+sq_j)-0.25 with bf16 hard error bound 0.004 + slack)
    const bool diag = (ti == tj);
    const int g = lane >> 2, t4 = lane & 3;
    float hi[4];
    #pragma unroll
    for (int ma = 0; ma < 2; ma++)
        #pragma unroll
        for (int h = 0; h < 2; h++)
            hi[ma * 2 + h] = 0.5f * sqI[wy * 32 + ma * 16 + g + h * 8];
    float hj[16];
    #pragma unroll
    for (int nf = 0; nf < 8; nf++)
        #pragma unroll
        for (int bb = 0; bb < 2; bb++)
            hj[nf * 2 + bb] = 0.5f * sqJ[wx * 64 + nf * 8 + t4 * 2 + bb] - 0.2551f;

    #pragma unroll
    for (int ma = 0; ma < 2; ma++)
        #pragma unroll
        for (int nf = 0; nf < 8; nf++)
            #pragma unroll
            for (int r = 0; r < 4; r++) {
                float v = acc[ma][nf][r];
                float thr = hi[ma * 2 + (r >> 1)] + hj[nf * 2 + (r & 1)];
                if (v > thr) {
                    int i = iBase + wy * 32 + ma * 16 + g + (r >> 1) * 8;
                    int j = jBase + wx * 64 + nf * 8 + t4 * 2 + (r & 1);
                    if (!diag || j > i) {
                        unsigned pos = atomicAdd(&g_cand_n, 1u);
                        if (pos < CAP) g_cand[pos] = (unsigned)((i << 13) | j);
                    }
                }
            }
}

// ---------------- kernel 4: exact fp32 fixup of flagged pairs --------------
__global__ void fixup_kernel(const float* __restrict__ classes,
                             const int* __restrict__ ids) {
    unsigned n = g_cand_n;
    if (n > CAP) n = CAP;
    int warpId = (blockIdx.x * blockDim.x + threadIdx.x) >> 5;
    int lane = threadIdx.x & 31;
    int nWarps = (gridDim.x * blockDim.x) >> 5;
    for (unsigned c = warpId; c < n; c += nWarps) {
        unsigned pk = g_cand[c];
        int i = pk >> 13, j = pk & 8191;
        float s = 0.0f;
        #pragma unroll 4
        for (int k = lane; k < D; k += 32)
            s += g_e[(size_t)i * D + k] * g_e[(size_t)j * D + k];
        #pragma unroll
        for (int o = 16; o > 0; o >>= 1) s += __shfl_down_sync(0xffffffff, s, o);
        if (lane == 0) {
            if (ids[i] != ids[j] && classes[i] == classes[j]) {
                float d2 = fmaxf(g_sq[i] + g_sq[j] - 2.0f * s, 0.0f);
                float term = fmaxf(0.0f, MARGIN - d2);
                if (term > 0.0f) atomicAdd(&g_hinge, term);
            }
        }
    }
}

// ---------------- kernel 5: BCE partials -----------------------------------
__global__ void bce_kernel(const float* __restrict__ outputs,
                           const float* __restrict__ classes) {
    float s = 0.0f;
    for (int i = blockIdx.x * blockDim.x + threadIdx.x; i < B;
         i += gridDim.x * blockDim.x) {
        float o = outputs[i], cl = classes[i];
        s += fmaxf(o, 0.0f) - o * cl + log1pf(expf(-fabsf(o)));
    }
    __shared__ float red[256];
    red[threadIdx.x] = s;
    __syncthreads();
    #pragma unroll
    for (int k = 128; k > 0; k >>= 1) {
        if (threadIdx.x < k) red[threadIdx.x] += red[threadIdx.x + k];
        __syncthreads();
    }
    if (threadIdx.x == 0) g_bce[blockIdx.x] = red[0];
}

// ---------------- kernel 6: final deterministic reduce ---------------------
// l = 0.25 * P_ord + H_upper ;  P_ord = 2 * sum_g P_id  =>  l = 0.5*sum(P_id) + H
__global__ void final_kernel(float* __restrict__ out) {
    int t = threadIdx.x;  // 256
    __shared__ float red[256];
    float s = 0.0f;
    for (int i = t; i < NUM_IDS; i += 256) s += g_pull[i];
    red[t] = s;
    __syncthreads();
    #pragma unroll
    for (int k = 128; k > 0; k >>= 1) {
        if (t < k) red[t] += red[t + k];
        __syncthreads();
    }
    if (t == 0) {
        float bsum = 0.0f;
        #pragma unroll
        for (int i = 0; i < BCE_BLOCKS; i++) bsum += g_bce[i];
        float l = 0.5f * red[0] + g_hinge;
        out[0] = bsum / (float)B + ALPHA * l;
    }
}

// ---------------------------------------------------------------------------
extern "C" void kernel_launch(void* const* d_in, const int* in_sizes, int n_in,
                              void* d_out, int out_size) {
    const float* outputs = (const float*)d_in[0];
    const float* classes = (const float*)d_in[1];
    const float* emb     = (const float*)d_in[2];
    const int*   ids     = (const int*)d_in[3];
    float* out = (float*)d_out;

    init_kernel<<<1, 1>>>();
    normalize_kernel<<<B, 128>>>(emb);
    pull_kernel<<<NUM_IDS, 256>>>(classes, ids);
    gram_kernel<<<dim3(NT, NT), 256>>>();
    fixup_kernel<<<64, 256>>>(classes, ids);
    bce_kernel<<<BCE_BLOCKS, 256>>>(outputs, classes);
    final_kernel<<<1, 256>>>(out);
}

// round 4
// speedup vs baseline: 4.7968x; 1.0252x over previous
#include <cuda_runtime.h>
#include <cuda_bf16.h>
#include <math.h>
#include <stdint.h>

#define B      8192
#define D      512
#define ALPHA  0.5f
#define MARGIN 0.5f
#define NUM_IDS 1024
#define CAP    (1u << 20)
#define MAXG   128

#define TM 128
#define TN 128
#define NT (B / TM)          // 64
#define BK 64                // fp8 elems per stage (64 bytes/row)
#define NSTAGE 4
#define STAGE_BYTES 16384    // A 8KB + B 8KB
#define SMEM_GRAM (NSTAGE * STAGE_BYTES + 1024)

// ---------------- scratch ----------------
__device__ float   g_e[B * D];      // normalized embeddings fp32 (exact math)
__device__ uint8_t g_e8[B * D];     // e4m3 copy (detector only)
__device__ float   g_sq[B];
__device__ float   g_pull[NUM_IDS];
__device__ unsigned g_cand[CAP];
__device__ unsigned g_cand_n;
__device__ float   g_hinge;

// ---------------- PTX helpers ----------------
__device__ __forceinline__ void cpa16(uint32_t dst, const void* src) {
    asm volatile("cp.async.cg.shared.global [%0], [%1], 16;\n" :: "r"(dst), "l"(src));
}
#define CP_COMMIT() asm volatile("cp.async.commit_group;\n" ::: "memory")
#define CP_WAIT2()  asm volatile("cp.async.wait_group 2;\n" ::: "memory")

__device__ __forceinline__ void ldsm4(uint32_t* r, uint32_t addr) {
    asm volatile("ldmatrix.sync.aligned.m8n8.x4.shared.b16 {%0,%1,%2,%3}, [%4];\n"
                 : "=r"(r[0]), "=r"(r[1]), "=r"(r[2]), "=r"(r[3]) : "r"(addr));
}
// m16n8k32 e4m3: fragments bit-identical to bf16 m16n8k16 with b16 -> 2x fp8
__device__ __forceinline__ void mma_fp8(float* d, const uint32_t* a,
                                        uint32_t b0, uint32_t b1) {
    asm volatile(
        "mma.sync.aligned.m16n8k32.row.col.f32.e4m3.e4m3.f32 "
        "{%0,%1,%2,%3}, {%4,%5,%6,%7}, {%8,%9}, {%0,%1,%2,%3};\n"
        : "+f"(d[0]), "+f"(d[1]), "+f"(d[2]), "+f"(d[3])
        : "r"(a[0]), "r"(a[1]), "r"(a[2]), "r"(a[3]), "r"(b0), "r"(b1));
}
__device__ __forceinline__ uint32_t pack_e4m3x4(float x, float y, float z, float w) {
    uint16_t lo, hi;
    asm("cvt.rn.satfinite.e4m3x2.f32 %0, %1, %2;" : "=h"(lo) : "f"(y), "f"(x));
    asm("cvt.rn.satfinite.e4m3x2.f32 %0, %1, %2;" : "=h"(hi) : "f"(w), "f"(z));
    return ((uint32_t)hi << 16) | lo;
}

// ---------------- kernel 1: normalize -> g_e, g_e8, g_sq (+init) ----------
__global__ void normalize_kernel(const float* __restrict__ emb) {
    int row = blockIdx.x;
    int t = threadIdx.x;  // 0..127
    if (row == 0 && t == 0) { g_cand_n = 0u; g_hinge = 0.0f; }
    float4 v = ((const float4*)(emb + (size_t)row * D))[t];
    float s = v.x * v.x + v.y * v.y + v.z * v.z + v.w * v.w;
    #pragma unroll
    for (int o = 16; o > 0; o >>= 1) s += __shfl_down_sync(0xffffffff, s, o);
    __shared__ float sm[4];
    if ((t & 31) == 0) sm[t >> 5] = s;
    __syncthreads();
    float tot = sm[0] + sm[1] + sm[2] + sm[3];
    float inv = 1.0f / fmaxf(sqrtf(tot), 1e-12f);
    float4 o4 = make_float4(v.x * inv, v.y * inv, v.z * inv, v.w * inv);
    ((float4*)(g_e + (size_t)row * D))[t] = o4;
    ((uint32_t*)g_e8)[row * (D / 4) + t] = pack_e4m3x4(o4.x, o4.y, o4.z, o4.w);
    if (t == 0) g_sq[row] = tot * inv * inv;
}

// ---------------- kernel 2: exact per-id pull term ----------------
__global__ void __launch_bounds__(256) pull_kernel(const float* __restrict__ classes,
                                                   const int* __restrict__ ids) {
    int g = blockIdx.x;
    int t = threadIdx.x;
    __shared__ unsigned mask[256];
    __shared__ int   list[MAXG];
    __shared__ float lcls[MAXG];
    __shared__ int   cnt_s;
    __shared__ float n0s, n1s, sq0s, sq1s;
    __shared__ float red[256];

    mask[t] = 0u;
    __syncthreads();
    #pragma unroll
    for (int it = 0; it < B / 256; it++) {
        int r = t + it * 256;
        if (ids[r] == g) atomicOr(&mask[r >> 5], 1u << (r & 31));
    }
    __syncthreads();
    if (t == 0) {
        int c = 0;
        float n0 = 0.f, n1 = 0.f, s0 = 0.f, s1 = 0.f;
        for (int w = 0; w < 256; w++) {
            unsigned m = mask[w];
            while (m) {
                int b = __ffs(m) - 1;
                m &= m - 1;
                int r = w * 32 + b;
                float cl = classes[r];
                float sq = g_sq[r];
                if (c < MAXG) { list[c] = r; lcls[c] = cl; }
                c++;
                if (cl == 0.0f) { n0 += 1.f; s0 += sq; }
                else            { n1 += 1.f; s1 += sq; }
            }
        }
        cnt_s = c; n0s = n0; n1s = n1; sq0s = s0; sq1s = s1;
    }
    __syncthreads();
    int cnt = cnt_s < MAXG ? cnt_s : MAXG;
    float a0 = 0.f, a1 = 0.f, b0 = 0.f, b1 = 0.f;
    for (int k = 0; k < cnt; k++) {
        int r = list[k];
        float cl = lcls[k];
        float v0 = g_e[(size_t)r * D + t];
        float v1 = g_e[(size_t)r * D + t + 256];
        if (cl == 0.0f) { a0 += v0; b0 += v1; }
        else            { a1 += v0; b1 += v1; }
    }
    red[t] = a0 * a1 + b0 * b1;
    __syncthreads();
    #pragma unroll
    for (int s = 128; s > 0; s >>= 1) {
        if (t < s) red[t] += red[t + s];
        __syncthreads();
    }
    if (t == 0)
        g_pull[g] = n1s * sq0s + n0s * sq1s - 2.0f * red[0];
}

// ---------------- kernel 3: fp8 Gram detector (legacy HMMA) ----------------
// 128x128 block tile, 8 warps (warp tile 32x64), 4-stage cp.async pipeline,
// 64B smem rows with conflict-free SW64 swizzle: grp ^ ((row>>1)&3).
__global__ void __launch_bounds__(256) gram_kernel() {
    const int ti = blockIdx.y, tj = blockIdx.x;
    if (tj < ti) return;

    extern __shared__ __align__(1024) unsigned char dsm[];
    uint32_t sRaw = (uint32_t)__cvta_generic_to_shared(dsm);
    uint32_t sBase = (sRaw + 1023u) & ~1023u;

    __shared__ float sqI[TM];
    __shared__ float thrJ[TN];

    const int tid = threadIdx.x;
    const int lane = tid & 31, warp = tid >> 5;
    const int wy = warp >> 1, wx = warp & 1;   // warp tile M=wy*32, N=wx*64
    const int iBase = ti * TM, jBase = tj * TN;

    if (tid < TM) sqI[tid] = g_sq[iBase + tid];
    else          thrJ[tid - TM] = 0.5f * g_sq[jBase + tid - TM] - 0.45f;

    float acc[2][8][4];
    #pragma unroll
    for (int m = 0; m < 2; m++)
        #pragma unroll
        for (int n = 0; n < 8; n++)
            #pragma unroll
            for (int r = 0; r < 4; r++) acc[m][n][r] = 0.0f;

    // cp.async plan: 1024 chunks of 16B per stage (A 512 + B 512), 4/thread
    uint32_t dsts[4];
    size_t   srcs[4];
    #pragma unroll
    for (int l = 0; l < 4; l++) {
        int c = tid + l * 256;
        bool isA = c < 512;
        int cc = c & 511;
        int row = cc >> 2, grp = cc & 3;
        dsts[l] = (isA ? 0u : 8192u) + (uint32_t)(row * 64) +
                  ((uint32_t)(grp ^ ((row >> 1) & 3)) << 4);
        srcs[l] = (size_t)((isA ? iBase : jBase) + row) * D + grp * 16;
    }
    auto loadStage = [&](int kb, int buf) {
        uint32_t base = sBase + (uint32_t)buf * STAGE_BYTES;
        #pragma unroll
        for (int l = 0; l < 4; l++)
            cpa16(base + dsts[l], g_e8 + srcs[l] + kb);
    };

    #pragma unroll
    for (int p = 0; p < 3; p++) {
        loadStage(p * BK, p);
        CP_COMMIT();
    }

    const int lrow = lane & 7;
    const int subh = (lane >> 3) & 1;
    const int subg = lane >> 4;

    #pragma unroll 1
    for (int s = 0; s < D / BK; s++) {
        CP_WAIT2();
        __syncthreads();
        if (s + 3 < D / BK) loadStage((s + 3) * BK, (s + 3) & 3);
        CP_COMMIT();

        const uint32_t base = sBase + (uint32_t)(s & 3) * STAGE_BYTES;
        #pragma unroll
        for (int ks = 0; ks < 2; ks++) {
            const int grp = 2 * ks + subg;
            uint32_t a[2][4];
            #pragma unroll
            for (int ma = 0; ma < 2; ma++) {
                int row = wy * 32 + ma * 16 + lrow + subh * 8;
                ldsm4(a[ma], base + row * 64 + ((grp ^ ((row >> 1) & 3)) << 4));
            }
            uint32_t bf[4][4];
            #pragma unroll
            for (int nb = 0; nb < 4; nb++) {
                int row = wx * 64 + nb * 16 + lrow + subh * 8;
                ldsm4(bf[nb], base + 8192 + row * 64 + ((grp ^ ((row >> 1) & 3)) << 4));
            }
            #pragma unroll
            for (int ma = 0; ma < 2; ma++)
                #pragma unroll
                for (int nb = 0; nb < 4; nb++) {
                    mma_fp8(acc[ma][2 * nb],     a[ma], bf[nb][0], bf[nb][2]);
                    mma_fp8(acc[ma][2 * nb + 1], a[ma], bf[nb][1], bf[nb][3]);
                }
        }
    }

    // epilogue: flag dot_fp8 > 0.5*(sq_i+sq_j) - 0.45 (covers boundary -0.25
    // with e4m3 dot error bound <= 0.18)
    const bool diag = (ti == tj);
    const int g = lane >> 2, t4 = lane & 3;
    float hi[4];
    #pragma unroll
    for (int ma = 0; ma < 2; ma++)
        #pragma unroll
        for (int h = 0; h < 2; h++)
            hi[ma * 2 + h] = 0.5f * sqI[wy * 32 + ma * 16 + g + h * 8];
    float hj[16];
    #pragma unroll
    for (int nf = 0; nf < 8; nf++)
        #pragma unroll
        for (int bb = 0; bb < 2; bb++)
            hj[nf * 2 + bb] = thrJ[wx * 64 + nf * 8 + t4 * 2 + bb];

    #pragma unroll
    for (int ma = 0; ma < 2; ma++)
        #pragma unroll
        for (int nf = 0; nf < 8; nf++)
            #pragma unroll
            for (int r = 0; r < 4; r++) {
                float v = acc[ma][nf][r];
                float thr = hi[ma * 2 + (r >> 1)] + hj[nf * 2 + (r & 1)];
                if (v > thr) {
                    int i = iBase + wy * 32 + ma * 16 + g + (r >> 1) * 8;
                    int j = jBase + wx * 64 + nf * 8 + t4 * 2 + (r & 1);
                    if (!diag || j > i) {
                        unsigned pos = atomicAdd(&g_cand_n, 1u);
                        if (pos < CAP) g_cand[pos] = (unsigned)((i << 13) | j);
                    }
                }
            }
}

// ---------------- kernel 4: exact fp32 fixup ----------------
__global__ void fixup_kernel(const float* __restrict__ classes,
                             const int* __restrict__ ids) {
    unsigned n = g_cand_n;
    if (n > CAP) n = CAP;
    int warpId = (blockIdx.x * blockDim.x + threadIdx.x) >> 5;
    int lane = threadIdx.x & 31;
    int nWarps = (gridDim.x * blockDim.x) >> 5;
    for (unsigned c = warpId; c < n; c += nWarps) {
        unsigned pk = g_cand[c];
        int i = pk >> 13, j = pk & 8191;
        float s = 0.0f;
        #pragma unroll 4
        for (int k = lane; k < D; k += 32)
            s += g_e[(size_t)i * D + k] * g_e[(size_t)j * D + k];
        #pragma unroll
        for (int o = 16; o > 0; o >>= 1) s += __shfl_down_sync(0xffffffff, s, o);
        if (lane == 0) {
            if (ids[i] != ids[j] && classes[i] == classes[j]) {
                float d2 = fmaxf(g_sq[i] + g_sq[j] - 2.0f * s, 0.0f);
                float term = fmaxf(0.0f, MARGIN - d2);
                if (term > 0.0f) atomicAdd(&g_hinge, term);
            }
        }
    }
}

// ---------------- kernel 5: BCE + final deterministic reduce ----------------
__global__ void final_kernel(const float* __restrict__ outputs,
                             const float* __restrict__ classes,
                             float* __restrict__ out) {
    int t = threadIdx.x;  // 256
    __shared__ float redP[256], redB[256];
    float sp = 0.0f;
    for (int i = t; i < NUM_IDS; i += 256) sp += g_pull[i];
    float sb = 0.0f;
    #pragma unroll
    for (int it = 0; it < B / 256; it++) {
        int i = t + it * 256;
        float o = outputs[i], cl = classes[i];
        sb += fmaxf(o, 0.0f) - o * cl + log1pf(expf(-fabsf(o)));
    }
    redP[t] = sp; redB[t] = sb;
    __syncthreads();
    #pragma unroll
    for (int k = 128; k > 0; k >>= 1) {
        if (t < k) { redP[t] += redP[t + k]; redB[t] += redB[t + k]; }
        __syncthreads();
    }
    if (t == 0) {
        float l = 0.5f * redP[0] + g_hinge;
        out[0] = redB[0] / (float)B + ALPHA * l;
    }
}

// ---------------------------------------------------------------------------
extern "C" void kernel_launch(void* const* d_in, const int* in_sizes, int n_in,
                              void* d_out, int out_size) {
    const float* outputs = (const float*)d_in[0];
    const float* classes = (const float*)d_in[1];
    const float* emb     = (const float*)d_in[2];
    const int*   ids     = (const int*)d_in[3];
    float* out = (float*)d_out;

    cudaFuncSetAttribute(gram_kernel,
                         cudaFuncAttributeMaxDynamicSharedMemorySize, SMEM_GRAM);

    normalize_kernel<<<B, 128>>>(emb);
    pull_kernel<<<NUM_IDS, 256>>>(classes, ids);
    gram_kernel<<<dim3(NT, NT), 256, SMEM_GRAM>>>();
    fixup_kernel<<<64, 256>>>(classes, ids);
    final_kernel<<<1, 256>>>(outputs, classes, out);
}

// round 5
// speedup vs baseline: 6.5930x; 1.3745x over previous
#include <cuda_runtime.h>
#include <cuda_bf16.h>
#include <math.h>
#include <stdint.h>

#define B      8192
#define D      512
#define ALPHA  0.5f
#define MARGIN 0.5f
#define NUM_IDS 1024
#define CAP    (1u << 20)
#define MAXG   128

#define TM 128
#define TN 128
#define BK 64                // fp8 elems per stage (64 bytes/row)
#define NSTAGE 4
#define STAGE_BYTES 16384    // A 8KB + B 8KB
#define SMEM_GRAM (NSTAGE * STAGE_BYTES + 1024)
#define PADROWS (66 * 128)   // padded permuted layout capacity (8448)

// ---------------- scratch ----------------
__device__ float   g_e[B * D];        // normalized embeddings fp32 (orig order)
__device__ uint8_t g_e8p[PADROWS * D];// e4m3 copy, class-partitioned + padded
__device__ float   g_sq[B];           // orig order
__device__ float   g_sqp[PADROWS];    // permuted (+100.0 sentinel on padding)
__device__ int     g_rank[B];         // orig -> padded pos
__device__ int     g_perm[PADROWS];   // padded pos -> orig (-1 pad)
__device__ int     g_T0, g_T1, g_base1;
__device__ float   g_pull[NUM_IDS];
__device__ unsigned g_cand[CAP];
__device__ unsigned g_cand_n;
__device__ float   g_hinge;

// ---------------- PTX helpers ----------------
__device__ __forceinline__ void cpa16(uint32_t dst, const void* src) {
    asm volatile("cp.async.cg.shared.global [%0], [%1], 16;\n" :: "r"(dst), "l"(src));
}
#define CP_COMMIT() asm volatile("cp.async.commit_group;\n" ::: "memory")
#define CP_WAIT2()  asm volatile("cp.async.wait_group 2;\n" ::: "memory")

__device__ __forceinline__ void ldsm4(uint32_t* r, uint32_t addr) {
    asm volatile("ldmatrix.sync.aligned.m8n8.x4.shared.b16 {%0,%1,%2,%3}, [%4];\n"
                 : "=r"(r[0]), "=r"(r[1]), "=r"(r[2]), "=r"(r[3]) : "r"(addr));
}
__device__ __forceinline__ void mma_fp8(float* d, const uint32_t* a,
                                        uint32_t b0, uint32_t b1) {
    asm volatile(
        "mma.sync.aligned.m16n8k32.row.col.f32.e4m3.e4m3.f32 "
        "{%0,%1,%2,%3}, {%4,%5,%6,%7}, {%8,%9}, {%0,%1,%2,%3};\n"
        : "+f"(d[0]), "+f"(d[1]), "+f"(d[2]), "+f"(d[3])
        : "r"(a[0]), "r"(a[1]), "r"(a[2]), "r"(a[3]), "r"(b0), "r"(b1));
}
__device__ __forceinline__ uint32_t pack_e4m3x4(float x, float y, float z, float w) {
    uint16_t lo, hi;
    asm("cvt.rn.satfinite.e4m3x2.f32 %0, %1, %2;" : "=h"(lo) : "f"(y), "f"(x));
    asm("cvt.rn.satfinite.e4m3x2.f32 %0, %1, %2;" : "=h"(hi) : "f"(w), "f"(z));
    return ((uint32_t)hi << 16) | lo;
}

// ---------------- kernel 0: stable class partition (single block) ----------
__global__ void __launch_bounds__(1024) partition_kernel(const float* __restrict__ classes) {
    __shared__ int s[1024];
    const int t = threadIdx.x;
    const int base = t * 8;
    int cls[8];
    int c0 = 0;
    #pragma unroll
    for (int k = 0; k < 8; k++) {
        cls[k] = (classes[base + k] == 0.0f) ? 1 : 0;
        c0 += cls[k];
    }
    s[t] = c0;
    __syncthreads();
    // Hillis-Steele inclusive scan
    for (int off = 1; off < 1024; off <<= 1) {
        int v = (t >= off) ? s[t - off] : 0;
        __syncthreads();
        s[t] += v;
        __syncthreads();
    }
    const int n0 = s[1023];
    const int pre0 = s[t] - c0;
    const int n1 = B - n0;
    const int T0 = (n0 + 127) >> 7;
    const int T1 = (n1 + 127) >> 7;
    const int base1 = T0 * 128;

    int p0 = pre0;
    int p1 = base1 + (base - pre0);
    #pragma unroll
    for (int k = 0; k < 8; k++) {
        int orig = base + k;
        int pos = cls[k] ? p0++ : p1++;
        g_rank[orig] = pos;
        g_perm[pos] = orig;
    }
    if (t == 0) { g_T0 = T0; g_T1 = T1; g_base1 = base1; }

    // padding rows: [n0, base1) and [base1+n1, base1+T1*128)
    for (int p = n0 + t; p < base1; p += 1024) {
        g_perm[p] = -1;
        g_sqp[p] = 100.0f;
        uint4 z = make_uint4(0, 0, 0, 0);
        #pragma unroll
        for (int q = 0; q < 32; q++)
            ((uint4*)(g_e8p + (size_t)p * D))[q] = z;
    }
    const int end1 = base1 + T1 * 128;
    for (int p = base1 + n1 + t; p < end1; p += 1024) {
        g_perm[p] = -1;
        g_sqp[p] = 100.0f;
        uint4 z = make_uint4(0, 0, 0, 0);
        #pragma unroll
        for (int q = 0; q < 32; q++)
            ((uint4*)(g_e8p + (size_t)p * D))[q] = z;
    }
}

// ---------------- kernel 1: normalize -> g_e, g_e8p (permuted), sq ---------
__global__ void normalize_kernel(const float* __restrict__ emb) {
    int row = blockIdx.x;
    int t = threadIdx.x;  // 0..127
    if (row == 0 && t == 0) { g_cand_n = 0u; g_hinge = 0.0f; }
    float4 v = ((const float4*)(emb + (size_t)row * D))[t];
    float s = v.x * v.x + v.y * v.y + v.z * v.z + v.w * v.w;
    #pragma unroll
    for (int o = 16; o > 0; o >>= 1) s += __shfl_down_sync(0xffffffff, s, o);
    __shared__ float sm[4];
    if ((t & 31) == 0) sm[t >> 5] = s;
    __syncthreads();
    float tot = sm[0] + sm[1] + sm[2] + sm[3];
    float inv = 1.0f / fmaxf(sqrtf(tot), 1e-12f);
    float4 o4 = make_float4(v.x * inv, v.y * inv, v.z * inv, v.w * inv);
    ((float4*)(g_e + (size_t)row * D))[t] = o4;
    int pr = g_rank[row];
    ((uint32_t*)g_e8p)[(size_t)pr * (D / 4) + t] = pack_e4m3x4(o4.x, o4.y, o4.z, o4.w);
    if (t == 0) {
        float sq = tot * inv * inv;
        g_sq[row] = sq;
        g_sqp[pr] = sq;
    }
}

// ---------------- kernel 2: exact per-id pull term ----------------
__global__ void __launch_bounds__(256) pull_kernel(const float* __restrict__ classes,
                                                   const int* __restrict__ ids) {
    int g = blockIdx.x;
    int t = threadIdx.x;
    __shared__ unsigned mask[256];
    __shared__ int   list[MAXG];
    __shared__ float lcls[MAXG];
    __shared__ int   cnt_s;
    __shared__ float n0s, n1s, sq0s, sq1s;
    __shared__ float red[256];

    mask[t] = 0u;
    __syncthreads();
    #pragma unroll
    for (int it = 0; it < B / 256; it++) {
        int r = t + it * 256;
        if (ids[r] == g) atomicOr(&mask[r >> 5], 1u << (r & 31));
    }
    __syncthreads();
    if (t == 0) {
        int c = 0;
        float n0 = 0.f, n1 = 0.f, s0 = 0.f, s1 = 0.f;
        for (int w = 0; w < 256; w++) {
            unsigned m = mask[w];
            while (m) {
                int b = __ffs(m) - 1;
                m &= m - 1;
                int r = w * 32 + b;
                float cl = classes[r];
                float sq = g_sq[r];
                if (c < MAXG) { list[c] = r; lcls[c] = cl; }
                c++;
                if (cl == 0.0f) { n0 += 1.f; s0 += sq; }
                else            { n1 += 1.f; s1 += sq; }
            }
        }
        cnt_s = c; n0s = n0; n1s = n1; sq0s = s0; sq1s = s1;
    }
    __syncthreads();
    int cnt = cnt_s < MAXG ? cnt_s : MAXG;
    float a0 = 0.f, a1 = 0.f, b0 = 0.f, b1 = 0.f;
    for (int k = 0; k < cnt; k++) {
        int r = list[k];
        float cl = lcls[k];
        float v0 = g_e[(size_t)r * D + t];
        float v1 = g_e[(size_t)r * D + t + 256];
        if (cl == 0.0f) { a0 += v0; b0 += v1; }
        else            { a1 += v0; b1 += v1; }
    }
    red[t] = a0 * a1 + b0 * b1;
    __syncthreads();
    #pragma unroll
    for (int s = 128; s > 0; s >>= 1) {
        if (t < s) red[t] += red[t + s];
        __syncthreads();
    }
    if (t == 0)
        g_pull[g] = n1s * sq0s + n0s * sq1s - 2.0f * red[0];
}

// ---------------- kernel 3: fp8 within-class Gram detector ----------------
// gridDim.z = class; triangular tiles (ti <= tj) inside each class block.
__global__ void __launch_bounds__(256) gram_kernel() {
    const int cls = blockIdx.z;
    const int T = cls ? g_T1 : g_T0;
    const int ti = blockIdx.y, tj = blockIdx.x;
    if (tj >= T || ti > tj) return;
    const int pbase = cls ? g_base1 : 0;

    extern __shared__ __align__(1024) unsigned char dsm[];
    uint32_t sRaw = (uint32_t)__cvta_generic_to_shared(dsm);
    uint32_t sBase = (sRaw + 1023u) & ~1023u;

    __shared__ float sqI[TM];
    __shared__ float thrJ[TN];

    const int tid = threadIdx.x;
    const int lane = tid & 31, warp = tid >> 5;
    const int wy = warp >> 1, wx = warp & 1;   // warp tile M=wy*32, N=wx*64
    const int iBase = pbase + ti * TM, jBase = pbase + tj * TN;

    if (tid < TM) sqI[tid] = g_sqp[iBase + tid];
    else          thrJ[tid - TM] = 0.5f * g_sqp[jBase + tid - TM] - 0.45f;

    float acc[2][8][4];
    #pragma unroll
    for (int m = 0; m < 2; m++)
        #pragma unroll
        for (int n = 0; n < 8; n++)
            #pragma unroll
            for (int r = 0; r < 4; r++) acc[m][n][r] = 0.0f;

    uint32_t dsts[4];
    size_t   srcs[4];
    #pragma unroll
    for (int l = 0; l < 4; l++) {
        int c = tid + l * 256;
        bool isA = c < 512;
        int cc = c & 511;
        int row = cc >> 2, grp = cc & 3;
        dsts[l] = (isA ? 0u : 8192u) + (uint32_t)(row * 64) +
                  ((uint32_t)(grp ^ ((row >> 1) & 3)) << 4);
        srcs[l] = (size_t)((isA ? iBase : jBase) + row) * D + grp * 16;
    }
    auto loadStage = [&](int kb, int buf) {
        uint32_t base = sBase + (uint32_t)buf * STAGE_BYTES;
        #pragma unroll
        for (int l = 0; l < 4; l++)
            cpa16(base + dsts[l], g_e8p + srcs[l] + kb);
    };

    #pragma unroll
    for (int p = 0; p < 3; p++) {
        loadStage(p * BK, p);
        CP_COMMIT();
    }

    const int lrow = lane & 7;
    const int subh = (lane >> 3) & 1;
    const int subg = lane >> 4;

    #pragma unroll 1
    for (int s = 0; s < D / BK; s++) {
        CP_WAIT2();
        __syncthreads();
        if (s + 3 < D / BK) loadStage((s + 3) * BK, (s + 3) & 3);
        CP_COMMIT();

        const uint32_t base = sBase + (uint32_t)(s & 3) * STAGE_BYTES;
        #pragma unroll
        for (int ks = 0; ks < 2; ks++) {
            const int grp = 2 * ks + subg;
            uint32_t a[2][4];
            #pragma unroll
            for (int ma = 0; ma < 2; ma++) {
                int row = wy * 32 + ma * 16 + lrow + subh * 8;
                ldsm4(a[ma], base + row * 64 + ((grp ^ ((row >> 1) & 3)) << 4));
            }
            uint32_t bf[4][4];
            #pragma unroll
            for (int nb = 0; nb < 4; nb++) {
                int row = wx * 64 + nb * 16 + lrow + subh * 8;
                ldsm4(bf[nb], base + 8192 + row * 64 + ((grp ^ ((row >> 1) & 3)) << 4));
            }
            #pragma unroll
            for (int ma = 0; ma < 2; ma++)
                #pragma unroll
                for (int nb = 0; nb < 4; nb++) {
                    mma_fp8(acc[ma][2 * nb],     a[ma], bf[nb][0], bf[nb][2]);
                    mma_fp8(acc[ma][2 * nb + 1], a[ma], bf[nb][1], bf[nb][3]);
                }
        }
    }

    // epilogue: flag dot_fp8 > 0.5*(sq_i+sq_j) - 0.45 in permuted positions
    const bool diag = (ti == tj);
    const int g = lane >> 2, t4 = lane & 3;
    float hi[4];
    #pragma unroll
    for (int ma = 0; ma < 2; ma++)
        #pragma unroll
        for (int h = 0; h < 2; h++)
            hi[ma * 2 + h] = 0.5f * sqI[wy * 32 + ma * 16 + g + h * 8];
    float hj[16];
    #pragma unroll
    for (int nf = 0; nf < 8; nf++)
        #pragma unroll
        for (int bb = 0; bb < 2; bb++)
            hj[nf * 2 + bb] = thrJ[wx * 64 + nf * 8 + t4 * 2 + bb];

    #pragma unroll
    for (int ma = 0; ma < 2; ma++)
        #pragma unroll
        for (int nf = 0; nf < 8; nf++)
            #pragma unroll
            for (int r = 0; r < 4; r++) {
                float v = acc[ma][nf][r];
                float thr = hi[ma * 2 + (r >> 1)] + hj[nf * 2 + (r & 1)];
                if (v > thr) {
                    int pi = iBase + wy * 32 + ma * 16 + g + (r >> 1) * 8;
                    int pj = jBase + wx * 64 + nf * 8 + t4 * 2 + (r & 1);
                    if (!diag || pj > pi) {
                        unsigned pos = atomicAdd(&g_cand_n, 1u);
                        if (pos < CAP)
                            g_cand[pos] = ((unsigned)pi << 14) | (unsigned)pj;
                    }
                }
            }
}

// ---------------- kernel 4: exact fp32 fixup ----------------
__global__ void fixup_kernel(const float* __restrict__ classes,
                             const int* __restrict__ ids) {
    unsigned n = g_cand_n;
    if (n > CAP) n = CAP;
    int warpId = (blockIdx.x * blockDim.x + threadIdx.x) >> 5;
    int lane = threadIdx.x & 31;
    int nWarps = (gridDim.x * blockDim.x) >> 5;
    for (unsigned c = warpId; c < n; c += nWarps) {
        unsigned pk = g_cand[c];
        int pi = pk >> 14, pj = pk & 16383;
        int i = g_perm[pi], j = g_perm[pj];
        if (i < 0 || j < 0) continue;
        float s = 0.0f;
        #pragma unroll 4
        for (int k = lane; k < D; k += 32)
            s += g_e[(size_t)i * D + k] * g_e[(size_t)j * D + k];
        #pragma unroll
        for (int o = 16; o > 0; o >>= 1) s += __shfl_down_sync(0xffffffff, s, o);
        if (lane == 0) {
            if (ids[i] != ids[j] && classes[i] == classes[j]) {
                float d2 = fmaxf(g_sq[i] + g_sq[j] - 2.0f * s, 0.0f);
                float term = fmaxf(0.0f, MARGIN - d2);
                if (term > 0.0f) atomicAdd(&g_hinge, term);
            }
        }
    }
}

// ---------------- kernel 5: BCE + final deterministic reduce ----------------
__global__ void final_kernel(const float* __restrict__ outputs,
                             const float* __restrict__ classes,
                             float* __restrict__ out) {
    int t = threadIdx.x;  // 256
    __shared__ float redP[256], redB[256];
    float sp = 0.0f;
    for (int i = t; i < NUM_IDS; i += 256) sp += g_pull[i];
    float sb = 0.0f;
    #pragma unroll
    for (int it = 0; it < B / 256; it++) {
        int i = t + it * 256;
        float o = outputs[i], cl = classes[i];
        sb += fmaxf(o, 0.0f) - o * cl + log1pf(expf(-fabsf(o)));
    }
    redP[t] = sp; redB[t] = sb;
    __syncthreads();
    #pragma unroll
    for (int k = 128; k > 0; k >>= 1) {
        if (t < k) { redP[t] += redP[t + k]; redB[t] += redB[t + k]; }
        __syncthreads();
    }
    if (t == 0) {
        float l = 0.5f * redP[0] + g_hinge;
        out[0] = redB[0] / (float)B + ALPHA * l;
    }
}

// ---------------------------------------------------------------------------
extern "C" void kernel_launch(void* const* d_in, const int* in_sizes, int n_in,
                              void* d_out, int out_size) {
    const float* outputs = (const float*)d_in[0];
    const float* classes = (const float*)d_in[1];
    const float* emb     = (const float*)d_in[2];
    const int*   ids     = (const int*)d_in[3];
    float* out = (float*)d_out;

    cudaFuncSetAttribute(gram_kernel,
                         cudaFuncAttributeMaxDynamicSharedMemorySize, SMEM_GRAM);

    partition_kernel<<<1, 1024>>>(classes);
    normalize_kernel<<<B, 128>>>(emb);
    pull_kernel<<<NUM_IDS, 256>>>(classes, ids);
    gram_kernel<<<dim3(64, 64, 2), 256, SMEM_GRAM>>>();
    fixup_kernel<<<64, 256>>>(classes, ids);
    final_kernel<<<1, 256>>>(outputs, classes, out);
}

// round 6
// speedup vs baseline: 8.1682x; 1.2389x over previous
#include <cuda_runtime.h>
#include <cuda_bf16.h>
#include <math.h>
#include <stdint.h>

#define B      8192
#define D      512
#define ALPHA  0.5f
#define MARGIN 0.5f
#define NUM_IDS 1024
#define CAP    (1u << 20)
#define MAXG   128

#define TM 128
#define TN 128
#define BK 64                // fp8 elems per stage (64 bytes/row)
#define NSTAGE 4
#define STAGE_BYTES 16384    // A 8KB + B 8KB
#define SMEM_GRAM (NSTAGE * STAGE_BYTES + 1024)
#define PADROWS (66 * 128)   // padded permuted layout capacity (8448)
#define TRI_MAX 2080         // tri(64): worst-case tiles per class

// ---------------- scratch ----------------
__device__ uint8_t g_e8p[PADROWS * D];// e4m3 copy, class-partitioned + padded
__device__ float   g_inv[B];          // 1/max(norm,1e-12) per row (orig order)
__device__ float   g_sq[B];           // ||e||^2, orig order
__device__ float   g_sqp[PADROWS];    // permuted (+100.0 sentinel on padding)
__device__ int     g_rank[B];         // orig -> padded pos
__device__ int     g_perm[PADROWS];   // padded pos -> orig (-1 pad)
__device__ int     g_T0, g_T1, g_base1;
__device__ float   g_pull[NUM_IDS];
__device__ unsigned g_cand[CAP];
__device__ unsigned g_cand_n;
__device__ float   g_hinge;

// ---------------- PTX helpers ----------------
__device__ __forceinline__ void cpa16(uint32_t dst, const void* src) {
    asm volatile("cp.async.cg.shared.global [%0], [%1], 16;\n" :: "r"(dst), "l"(src));
}
#define CP_COMMIT() asm volatile("cp.async.commit_group;\n" ::: "memory")
#define CP_WAIT2()  asm volatile("cp.async.wait_group 2;\n" ::: "memory")

__device__ __forceinline__ void ldsm4(uint32_t* r, uint32_t addr) {
    asm volatile("ldmatrix.sync.aligned.m8n8.x4.shared.b16 {%0,%1,%2,%3}, [%4];\n"
                 : "=r"(r[0]), "=r"(r[1]), "=r"(r[2]), "=r"(r[3]) : "r"(addr));
}
__device__ __forceinline__ void mma_fp8(float* d, const uint32_t* a,
                                        uint32_t b0, uint32_t b1) {
    asm volatile(
        "mma.sync.aligned.m16n8k32.row.col.f32.e4m3.e4m3.f32 "
        "{%0,%1,%2,%3}, {%4,%5,%6,%7}, {%8,%9}, {%0,%1,%2,%3};\n"
        : "+f"(d[0]), "+f"(d[1]), "+f"(d[2]), "+f"(d[3])
        : "r"(a[0]), "r"(a[1]), "r"(a[2]), "r"(a[3]), "r"(b0), "r"(b1));
}
__device__ __forceinline__ uint32_t pack_e4m3x4(float x, float y, float z, float w) {
    uint16_t lo, hi;
    asm("cvt.rn.satfinite.e4m3x2.f32 %0, %1, %2;" : "=h"(lo) : "f"(y), "f"(x));
    asm("cvt.rn.satfinite.e4m3x2.f32 %0, %1, %2;" : "=h"(hi) : "f"(w), "f"(z));
    return ((uint32_t)hi << 16) | lo;
}

// ---------------- kernel 0: stable class partition (single block) ----------
__global__ void __launch_bounds__(1024) partition_kernel(const float* __restrict__ classes) {
    __shared__ int s[1024];
    const int t = threadIdx.x;
    const int base = t * 8;
    int cls[8];
    int c0 = 0;
    #pragma unroll
    for (int k = 0; k < 8; k++) {
        cls[k] = (classes[base + k] == 0.0f) ? 1 : 0;
        c0 += cls[k];
    }
    s[t] = c0;
    __syncthreads();
    for (int off = 1; off < 1024; off <<= 1) {
        int v = (t >= off) ? s[t - off] : 0;
        __syncthreads();
        s[t] += v;
        __syncthreads();
    }
    const int n0 = s[1023];
    const int pre0 = s[t] - c0;
    const int n1 = B - n0;
    const int T0 = (n0 + 127) >> 7;
    const int T1 = (n1 + 127) >> 7;
    const int base1 = T0 * 128;

    int p0 = pre0;
    int p1 = base1 + (base - pre0);
    #pragma unroll
    for (int k = 0; k < 8; k++) {
        int orig = base + k;
        int pos = cls[k] ? p0++ : p1++;
        g_rank[orig] = pos;
        g_perm[pos] = orig;
    }
    if (t == 0) { g_T0 = T0; g_T1 = T1; g_base1 = base1; }

    for (int p = n0 + t; p < base1; p += 1024) {
        g_perm[p] = -1;
        g_sqp[p] = 100.0f;
        uint4 z = make_uint4(0, 0, 0, 0);
        #pragma unroll
        for (int q = 0; q < 32; q++)
            ((uint4*)(g_e8p + (size_t)p * D))[q] = z;
    }
    const int end1 = base1 + T1 * 128;
    for (int p = base1 + n1 + t; p < end1; p += 1024) {
        g_perm[p] = -1;
        g_sqp[p] = 100.0f;
        uint4 z = make_uint4(0, 0, 0, 0);
        #pragma unroll
        for (int q = 0; q < 32; q++)
            ((uint4*)(g_e8p + (size_t)p * D))[q] = z;
    }
}

// ---------------- kernel 1: normalize -> g_e8p (permuted), inv, sq ---------
__global__ void normalize_kernel(const float* __restrict__ emb) {
    int row = blockIdx.x;
    int t = threadIdx.x;  // 0..127
    if (row == 0 && t == 0) { g_cand_n = 0u; g_hinge = 0.0f; }
    float4 v = ((const float4*)(emb + (size_t)row * D))[t];
    float s = v.x * v.x + v.y * v.y + v.z * v.z + v.w * v.w;
    #pragma unroll
    for (int o = 16; o > 0; o >>= 1) s += __shfl_down_sync(0xffffffff, s, o);
    __shared__ float sm[4];
    if ((t & 31) == 0) sm[t >> 5] = s;
    __syncthreads();
    float tot = sm[0] + sm[1] + sm[2] + sm[3];
    float inv = 1.0f / fmaxf(sqrtf(tot), 1e-12f);
    float4 o4 = make_float4(v.x * inv, v.y * inv, v.z * inv, v.w * inv);
    int pr = g_rank[row];
    ((uint32_t*)g_e8p)[(size_t)pr * (D / 4) + t] = pack_e4m3x4(o4.x, o4.y, o4.z, o4.w);
    if (t == 0) {
        float sq = tot * inv * inv;
        g_inv[row] = inv;
        g_sq[row] = sq;
        g_sqp[pr] = sq;
    }
}

// ---------------- kernel 2: exact per-id pull term ----------------
__global__ void __launch_bounds__(256) pull_kernel(const float* __restrict__ classes,
                                                   const int* __restrict__ ids,
                                                   const float* __restrict__ emb) {
    int g = blockIdx.x;
    int t = threadIdx.x;
    __shared__ unsigned mask[256];
    __shared__ int   list[MAXG];
    __shared__ float lcls[MAXG];
    __shared__ float linv[MAXG];
    __shared__ int   cnt_s;
    __shared__ float n0s, n1s, sq0s, sq1s;
    __shared__ float red[256];

    mask[t] = 0u;
    __syncthreads();
    #pragma unroll
    for (int it = 0; it < B / 256; it++) {
        int r = t + it * 256;
        if (ids[r] == g) atomicOr(&mask[r >> 5], 1u << (r & 31));
    }
    __syncthreads();
    if (t == 0) {
        int c = 0;
        float n0 = 0.f, n1 = 0.f, s0 = 0.f, s1 = 0.f;
        for (int w = 0; w < 256; w++) {
            unsigned m = mask[w];
            while (m) {
                int b = __ffs(m) - 1;
                m &= m - 1;
                int r = w * 32 + b;
                float cl = classes[r];
                float sq = g_sq[r];
                if (c < MAXG) { list[c] = r; lcls[c] = cl; linv[c] = g_inv[r]; }
                c++;
                if (cl == 0.0f) { n0 += 1.f; s0 += sq; }
                else            { n1 += 1.f; s1 += sq; }
            }
        }
        cnt_s = c; n0s = n0; n1s = n1; sq0s = s0; sq1s = s1;
    }
    __syncthreads();
    int cnt = cnt_s < MAXG ? cnt_s : MAXG;
    float a0 = 0.f, a1 = 0.f, b0 = 0.f, b1 = 0.f;
    for (int k = 0; k < cnt; k++) {
        int r = list[k];
        float cl = lcls[k];
        float iv = linv[k];
        float v0 = emb[(size_t)r * D + t] * iv;
        float v1 = emb[(size_t)r * D + t + 256] * iv;
        if (cl == 0.0f) { a0 += v0; b0 += v1; }
        else            { a1 += v0; b1 += v1; }
    }
    red[t] = a0 * a1 + b0 * b1;
    __syncthreads();
    #pragma unroll
    for (int s = 128; s > 0; s >>= 1) {
        if (t < s) red[t] += red[t + s];
        __syncthreads();
    }
    if (t == 0)
        g_pull[g] = n1s * sq0s + n0s * sq1s - 2.0f * red[0];
}

// ---------------- kernel 3: fp8 within-class Gram detector ----------------
// 1D triangular grid per class: blockIdx.x -> (ti, tj) with ti <= tj.
__global__ void __launch_bounds__(256, 2) gram_kernel() {
    const int cls = blockIdx.y;
    const int T = cls ? g_T1 : g_T0;
    // triangular decode
    int k = blockIdx.x;
    int tj = (int)((__fsqrt_rn(8.0f * (float)k + 1.0f) - 1.0f) * 0.5f);
    while ((tj + 1) * (tj + 2) / 2 <= k) ++tj;
    while (tj * (tj + 1) / 2 > k) --tj;
    const int ti = k - tj * (tj + 1) / 2;
    if (tj >= T) return;
    const int pbase = cls ? g_base1 : 0;

    extern __shared__ __align__(1024) unsigned char dsm[];
    uint32_t sRaw = (uint32_t)__cvta_generic_to_shared(dsm);
    uint32_t sBase = (sRaw + 1023u) & ~1023u;

    __shared__ float sqI[TM];
    __shared__ float thrJ[TN];

    const int tid = threadIdx.x;
    const int lane = tid & 31, warp = tid >> 5;
    const int wy = warp >> 1, wx = warp & 1;   // warp tile M=wy*32, N=wx*64
    const int iBase = pbase + ti * TM, jBase = pbase + tj * TN;

    if (tid < TM) sqI[tid] = g_sqp[iBase + tid];
    else          thrJ[tid - TM] = 0.5f * g_sqp[jBase + tid - TM] - 0.45f;

    float acc[2][8][4];
    #pragma unroll
    for (int m = 0; m < 2; m++)
        #pragma unroll
        for (int n = 0; n < 8; n++)
            #pragma unroll
            for (int r = 0; r < 4; r++) acc[m][n][r] = 0.0f;

    uint32_t dsts[4];
    size_t   srcs[4];
    #pragma unroll
    for (int l = 0; l < 4; l++) {
        int c = tid + l * 256;
        bool isA = c < 512;
        int cc = c & 511;
        int row = cc >> 2, grp = cc & 3;
        dsts[l] = (isA ? 0u : 8192u) + (uint32_t)(row * 64) +
                  ((uint32_t)(grp ^ ((row >> 1) & 3)) << 4);
        srcs[l] = (size_t)((isA ? iBase : jBase) + row) * D + grp * 16;
    }
    auto loadStage = [&](int kb, int buf) {
        uint32_t base = sBase + (uint32_t)buf * STAGE_BYTES;
        #pragma unroll
        for (int l = 0; l < 4; l++)
            cpa16(base + dsts[l], g_e8p + srcs[l] + kb);
    };

    #pragma unroll
    for (int p = 0; p < 3; p++) {
        loadStage(p * BK, p);
        CP_COMMIT();
    }

    const int lrow = lane & 7;
    const int subh = (lane >> 3) & 1;
    const int subg = lane >> 4;

    #pragma unroll 1
    for (int s = 0; s < D / BK; s++) {
        CP_WAIT2();
        __syncthreads();
        if (s + 3 < D / BK) loadStage((s + 3) * BK, (s + 3) & 3);
        CP_COMMIT();

        const uint32_t base = sBase + (uint32_t)(s & 3) * STAGE_BYTES;
        #pragma unroll
        for (int ks = 0; ks < 2; ks++) {
            const int grp = 2 * ks + subg;
            uint32_t a[2][4];
            #pragma unroll
            for (int ma = 0; ma < 2; ma++) {
                int row = wy * 32 + ma * 16 + lrow + subh * 8;
                ldsm4(a[ma], base + row * 64 + ((grp ^ ((row >> 1) & 3)) << 4));
            }
            uint32_t bf[4][4];
            #pragma unroll
            for (int nb = 0; nb < 4; nb++) {
                int row = wx * 64 + nb * 16 + lrow + subh * 8;
                ldsm4(bf[nb], base + 8192 + row * 64 + ((grp ^ ((row >> 1) & 3)) << 4));
            }
            #pragma unroll
            for (int ma = 0; ma < 2; ma++)
                #pragma unroll
                for (int nb = 0; nb < 4; nb++) {
                    mma_fp8(acc[ma][2 * nb],     a[ma], bf[nb][0], bf[nb][2]);
                    mma_fp8(acc[ma][2 * nb + 1], a[ma], bf[nb][1], bf[nb][3]);
                }
        }
    }

    // epilogue: flag dot_fp8 > 0.5*(sq_i+sq_j) - 0.45 in permuted positions
    const bool diag = (ti == tj);
    const int g = lane >> 2, t4 = lane & 3;
    float hi[4];
    #pragma unroll
    for (int ma = 0; ma < 2; ma++)
        #pragma unroll
        for (int h = 0; h < 2; h++)
            hi[ma * 2 + h] = 0.5f * sqI[wy * 32 + ma * 16 + g + h * 8];
    float hj[16];
    #pragma unroll
    for (int nf = 0; nf < 8; nf++)
        #pragma unroll
        for (int bb = 0; bb < 2; bb++)
            hj[nf * 2 + bb] = thrJ[wx * 64 + nf * 8 + t4 * 2 + bb];

    #pragma unroll
    for (int ma = 0; ma < 2; ma++)
        #pragma unroll
        for (int nf = 0; nf < 8; nf++)
            #pragma unroll
            for (int r = 0; r < 4; r++) {
                float v = acc[ma][nf][r];
                float thr = hi[ma * 2 + (r >> 1)] + hj[nf * 2 + (r & 1)];
                if (v > thr) {
                    int pi = iBase + wy * 32 + ma * 16 + g + (r >> 1) * 8;
                    int pj = jBase + wx * 64 + nf * 8 + t4 * 2 + (r & 1);
                    if (!diag || pj > pi) {
                        unsigned pos = atomicAdd(&g_cand_n, 1u);
                        if (pos < CAP)
                            g_cand[pos] = ((unsigned)pi << 14) | (unsigned)pj;
                    }
                }
            }
}

// ---------------- kernel 4: exact fp32 fixup ----------------
__global__ void fixup_kernel(const float* __restrict__ classes,
                             const int* __restrict__ ids,
                             const float* __restrict__ emb) {
    unsigned n = g_cand_n;
    if (n > CAP) n = CAP;
    int warpId = (blockIdx.x * blockDim.x + threadIdx.x) >> 5;
    int lane = threadIdx.x & 31;
    int nWarps = (gridDim.x * blockDim.x) >> 5;
    for (unsigned c = warpId; c < n; c += nWarps) {
        unsigned pk = g_cand[c];
        int pi = pk >> 14, pj = pk & 16383;
        int i = g_perm[pi], j = g_perm[pj];
        if (i < 0 || j < 0) continue;
        float inv_i = g_inv[i], inv_j = g_inv[j];
        float s = 0.0f;
        #pragma unroll 4
        for (int k = lane; k < D; k += 32) {
            float a = emb[(size_t)i * D + k] * inv_i;
            float b = emb[(size_t)j * D + k] * inv_j;
            s += a * b;
        }
        #pragma unroll
        for (int o = 16; o > 0; o >>= 1) s += __shfl_down_sync(0xffffffff, s, o);
        if (lane == 0) {
            if (ids[i] != ids[j] && classes[i] == classes[j]) {
                float d2 = fmaxf(g_sq[i] + g_sq[j] - 2.0f * s, 0.0f);
                float term = fmaxf(0.0f, MARGIN - d2);
                if (term > 0.0f) atomicAdd(&g_hinge, term);
            }
        }
    }
}

// ---------------- kernel 5: BCE + final deterministic reduce ----------------
__global__ void final_kernel(const float* __restrict__ outputs,
                             const float* __restrict__ classes,
                             float* __restrict__ out) {
    int t = threadIdx.x;  // 256
    __shared__ float redP[256], redB[256];
    float sp = 0.0f;
    for (int i = t; i < NUM_IDS; i += 256) sp += g_pull[i];
    float sb = 0.0f;
    #pragma unroll
    for (int it = 0; it < B / 256; it++) {
        int i = t + it * 256;
        float o = outputs[i], cl = classes[i];
        sb += fmaxf(o, 0.0f) - o * cl + log1pf(expf(-fabsf(o)));
    }
    redP[t] = sp; redB[t] = sb;
    __syncthreads();
    #pragma unroll
    for (int k = 128; k > 0; k >>= 1) {
        if (t < k) { redP[t] += redP[t + k]; redB[t] += redB[t + k]; }
        __syncthreads();
    }
    if (t == 0) {
        float l = 0.5f * redP[0] + g_hinge;
        out[0] = redB[0] / (float)B + ALPHA * l;
    }
}

// ---------------------------------------------------------------------------
extern "C" void kernel_launch(void* const* d_in, const int* in_sizes, int n_in,
                              void* d_out, int out_size) {
    const float* outputs = (const float*)d_in[0];
    const float* classes = (const float*)d_in[1];
    const float* emb     = (const float*)d_in[2];
    const int*   ids     = (const int*)d_in[3];
    float* out = (float*)d_out;

    cudaFuncSetAttribute(gram_kernel,
                         cudaFuncAttributeMaxDynamicSharedMemorySize, SMEM_GRAM);

    partition_kernel<<<1, 1024>>>(classes);
    normalize_kernel<<<B, 128>>>(emb);
    pull_kernel<<<NUM_IDS, 256>>>(classes, ids, emb);
    gram_kernel<<<dim3(TRI_MAX, 2), 256, SMEM_GRAM>>>();
    fixup_kernel<<<64, 256>>>(classes, ids, emb);
    final_kernel<<<1, 256>>>(outputs, classes, out);
}

// round 7
// speedup vs baseline: 8.6864x; 1.0634x over previous
#include <cuda_runtime.h>
#include <cuda_bf16.h>
#include <math.h>
#include <stdint.h>

#define B      8192
#define D      512
#define ALPHA  0.5f
#define MARGIN 0.5f
#define NUM_IDS 1024
#define CAP    (1u << 20)
#define MAXG   128

#define TM 128
#define TN 128
#define BK 64                // fp8 elems per stage (64 bytes/row)
#define NSTAGE 4
#define STAGE_BYTES 16384    // A 8KB + B 8KB
#define SMEM_GRAM (NSTAGE * STAGE_BYTES + 1024)
#define PADROWS (66 * 128)   // padded permuted layout capacity (8448)
#define TRI_MAX 2080         // tri(64): worst-case tiles per class

// ---------------- scratch ----------------
__device__ uint8_t g_e8p[PADROWS * D];// e4m3 copy, class-partitioned + padded
__device__ float   g_inv[B];          // 1/max(norm,1e-12) per row (orig order)
__device__ float   g_sq[B];           // ||e||^2, orig order
__device__ float   g_sqp[PADROWS];    // permuted (+100.0 sentinel on padding)
__device__ int     g_rank[B];         // orig -> padded pos
__device__ int     g_perm[PADROWS];   // padded pos -> orig (-1 pad)
__device__ int     g_T0, g_T1, g_base1;
__device__ float   g_pull[NUM_IDS];
__device__ unsigned g_cand[CAP];
__device__ unsigned g_cand_n;
__device__ float   g_hinge;

// ---------------- PTX helpers ----------------
__device__ __forceinline__ void cpa16(uint32_t dst, const void* src) {
    asm volatile("cp.async.cg.shared.global [%0], [%1], 16;\n" :: "r"(dst), "l"(src));
}
#define CP_COMMIT() asm volatile("cp.async.commit_group;\n" ::: "memory")
#define CP_WAIT2()  asm volatile("cp.async.wait_group 2;\n" ::: "memory")

__device__ __forceinline__ void ldsm4(uint32_t* r, uint32_t addr) {
    asm volatile("ldmatrix.sync.aligned.m8n8.x4.shared.b16 {%0,%1,%2,%3}, [%4];\n"
                 : "=r"(r[0]), "=r"(r[1]), "=r"(r[2]), "=r"(r[3]) : "r"(addr));
}
__device__ __forceinline__ void mma_fp8(float* d, const uint32_t* a,
                                        uint32_t b0, uint32_t b1) {
    asm volatile(
        "mma.sync.aligned.m16n8k32.row.col.f32.e4m3.e4m3.f32 "
        "{%0,%1,%2,%3}, {%4,%5,%6,%7}, {%8,%9}, {%0,%1,%2,%3};\n"
        : "+f"(d[0]), "+f"(d[1]), "+f"(d[2]), "+f"(d[3])
        : "r"(a[0]), "r"(a[1]), "r"(a[2]), "r"(a[3]), "r"(b0), "r"(b1));
}
__device__ __forceinline__ uint32_t pack_e4m3x4(float x, float y, float z, float w) {
    uint16_t lo, hi;
    asm("cvt.rn.satfinite.e4m3x2.f32 %0, %1, %2;" : "=h"(lo) : "f"(y), "f"(x));
    asm("cvt.rn.satfinite.e4m3x2.f32 %0, %1, %2;" : "=h"(hi) : "f"(w), "f"(z));
    return ((uint32_t)hi << 16) | lo;
}

// ---------------- kernel 0: stable class partition (single block) ----------
__global__ void __launch_bounds__(1024) partition_kernel(const float* __restrict__ classes) {
    __shared__ int s[1024];
    const int t = threadIdx.x;
    const int base = t * 8;
    int cls[8];
    int c0 = 0;
    #pragma unroll
    for (int k = 0; k < 8; k++) {
        cls[k] = (classes[base + k] == 0.0f) ? 1 : 0;
        c0 += cls[k];
    }
    s[t] = c0;
    __syncthreads();
    for (int off = 1; off < 1024; off <<= 1) {
        int v = (t >= off) ? s[t - off] : 0;
        __syncthreads();
        s[t] += v;
        __syncthreads();
    }
    const int n0 = s[1023];
    const int pre0 = s[t] - c0;
    const int n1 = B - n0;
    const int T0 = (n0 + 127) >> 7;
    const int T1 = (n1 + 127) >> 7;
    const int base1 = T0 * 128;

    int p0 = pre0;
    int p1 = base1 + (base - pre0);
    #pragma unroll
    for (int k = 0; k < 8; k++) {
        int orig = base + k;
        int pos = cls[k] ? p0++ : p1++;
        g_rank[orig] = pos;
        g_perm[pos] = orig;
    }
    if (t == 0) { g_T0 = T0; g_T1 = T1; g_base1 = base1; }

    for (int p = n0 + t; p < base1; p += 1024) {
        g_perm[p] = -1;
        g_sqp[p] = 100.0f;
        uint4 z = make_uint4(0, 0, 0, 0);
        #pragma unroll
        for (int q = 0; q < 32; q++)
            ((uint4*)(g_e8p + (size_t)p * D))[q] = z;
    }
    const int end1 = base1 + T1 * 128;
    for (int p = base1 + n1 + t; p < end1; p += 1024) {
        g_perm[p] = -1;
        g_sqp[p] = 100.0f;
        uint4 z = make_uint4(0, 0, 0, 0);
        #pragma unroll
        for (int q = 0; q < 32; q++)
            ((uint4*)(g_e8p + (size_t)p * D))[q] = z;
    }
}

// ---------------- kernel 1: normalize -> g_e8p (permuted), inv, sq ---------
__global__ void normalize_kernel(const float* __restrict__ emb) {
    int row = blockIdx.x;
    int t = threadIdx.x;  // 0..127
    if (row == 0 && t == 0) { g_cand_n = 0u; g_hinge = 0.0f; }
    float4 v = ((const float4*)(emb + (size_t)row * D))[t];
    float s = v.x * v.x + v.y * v.y + v.z * v.z + v.w * v.w;
    #pragma unroll
    for (int o = 16; o > 0; o >>= 1) s += __shfl_down_sync(0xffffffff, s, o);
    __shared__ float sm[4];
    if ((t & 31) == 0) sm[t >> 5] = s;
    __syncthreads();
    float tot = sm[0] + sm[1] + sm[2] + sm[3];
    float inv = 1.0f / fmaxf(sqrtf(tot), 1e-12f);
    float4 o4 = make_float4(v.x * inv, v.y * inv, v.z * inv, v.w * inv);
    int pr = g_rank[row];
    ((uint32_t*)g_e8p)[(size_t)pr * (D / 4) + t] = pack_e4m3x4(o4.x, o4.y, o4.z, o4.w);
    if (t == 0) {
        float sq = tot * inv * inv;
        g_inv[row] = inv;
        g_sq[row] = sq;
        g_sqp[pr] = sq;
    }
}

// ---------------- kernel 2: exact per-id pull term ----------------
__global__ void __launch_bounds__(256) pull_kernel(const float* __restrict__ classes,
                                                   const int* __restrict__ ids,
                                                   const float* __restrict__ emb) {
    int g = blockIdx.x;
    int t = threadIdx.x;
    __shared__ unsigned mask[256];
    __shared__ int   list[MAXG];
    __shared__ float lcls[MAXG];
    __shared__ float linv[MAXG];
    __shared__ int   cnt_s;
    __shared__ float n0s, n1s, sq0s, sq1s;
    __shared__ float red[256];

    mask[t] = 0u;
    __syncthreads();
    #pragma unroll
    for (int it = 0; it < B / 256; it++) {
        int r = t + it * 256;
        if (ids[r] == g) atomicOr(&mask[r >> 5], 1u << (r & 31));
    }
    __syncthreads();
    if (t == 0) {
        int c = 0;
        float n0 = 0.f, n1 = 0.f, s0 = 0.f, s1 = 0.f;
        for (int w = 0; w < 256; w++) {
            unsigned m = mask[w];
            while (m) {
                int b = __ffs(m) - 1;
                m &= m - 1;
                int r = w * 32 + b;
                float cl = classes[r];
                float sq = g_sq[r];
                if (c < MAXG) { list[c] = r; lcls[c] = cl; linv[c] = g_inv[r]; }
                c++;
                if (cl == 0.0f) { n0 += 1.f; s0 += sq; }
                else            { n1 += 1.f; s1 += sq; }
            }
        }
        cnt_s = c; n0s = n0; n1s = n1; sq0s = s0; sq1s = s1;
    }
    __syncthreads();
    int cnt = cnt_s < MAXG ? cnt_s : MAXG;
    float a0 = 0.f, a1 = 0.f, b0 = 0.f, b1 = 0.f;
    for (int k = 0; k < cnt; k++) {
        int r = list[k];
        float cl = lcls[k];
        float iv = linv[k];
        float v0 = emb[(size_t)r * D + t] * iv;
        float v1 = emb[(size_t)r * D + t + 256] * iv;
        if (cl == 0.0f) { a0 += v0; b0 += v1; }
        else            { a1 += v0; b1 += v1; }
    }
    red[t] = a0 * a1 + b0 * b1;
    __syncthreads();
    #pragma unroll
    for (int s = 128; s > 0; s >>= 1) {
        if (t < s) red[t] += red[t + s];
        __syncthreads();
    }
    if (t == 0)
        g_pull[g] = n1s * sq0s + n0s * sq1s - 2.0f * red[0];
}

// ---------------- kernel 3: fp8 within-class Gram detector ----------------
// 1D triangular grid per class; all ldmatrix offsets hoisted out of K-loop.
__global__ void __launch_bounds__(256, 2) gram_kernel() {
    const int cls = blockIdx.y;
    const int T = cls ? g_T1 : g_T0;
    int k = blockIdx.x;
    int tj = (int)((__fsqrt_rn(8.0f * (float)k + 1.0f) - 1.0f) * 0.5f);
    while ((tj + 1) * (tj + 2) / 2 <= k) ++tj;
    while (tj * (tj + 1) / 2 > k) --tj;
    const int ti = k - tj * (tj + 1) / 2;
    if (tj >= T) return;
    const int pbase = cls ? g_base1 : 0;

    extern __shared__ __align__(1024) unsigned char dsm[];
    uint32_t sRaw = (uint32_t)__cvta_generic_to_shared(dsm);
    uint32_t sBase = (sRaw + 1023u) & ~1023u;

    __shared__ float sqI[TM];
    __shared__ float thrJ[TN];

    const int tid = threadIdx.x;
    const int lane = tid & 31, warp = tid >> 5;
    const int wy = warp >> 1, wx = warp & 1;   // warp tile M=wy*32, N=wx*64
    const int iBase = pbase + ti * TM, jBase = pbase + tj * TN;

    if (tid < TM) sqI[tid] = g_sqp[iBase + tid];
    else          thrJ[tid - TM] = 0.5f * g_sqp[jBase + tid - TM] - 0.45f;

    float acc[2][8][4];
    #pragma unroll
    for (int m = 0; m < 2; m++)
        #pragma unroll
        for (int n = 0; n < 8; n++)
            #pragma unroll
            for (int r = 0; r < 4; r++) acc[m][n][r] = 0.0f;

    // ---- hoisted cp.async plan: fixed dst offsets, walking src pointers ----
    uint32_t dsts[4];
    const uint8_t* srcp[4];
    #pragma unroll
    for (int l = 0; l < 4; l++) {
        int c = tid + l * 256;
        bool isA = c < 512;
        int cc = c & 511;
        int row = cc >> 2, grp = cc & 3;
        dsts[l] = (isA ? 0u : 8192u) + (uint32_t)(row * 64) +
                  ((uint32_t)(grp ^ ((row >> 1) & 3)) << 4);
        srcp[l] = g_e8p + (size_t)((isA ? iBase : jBase) + row) * D + grp * 16;
    }
    // monotone call order -> advance src pointers by BK per stage issued
    auto loadStage = [&](int buf) {
        uint32_t base = sBase + (uint32_t)buf * STAGE_BYTES;
        #pragma unroll
        for (int l = 0; l < 4; l++) {
            cpa16(base + dsts[l], srcp[l]);
            srcp[l] += BK;
        }
    };

    // ---- hoisted ldmatrix offsets (stage-invariant) ----
    const int lrow = lane & 7;
    const int subh = (lane >> 3) & 1;
    const int subg = lane >> 4;
    uint32_t offA[2][2], offB[2][4];
    #pragma unroll
    for (int ks = 0; ks < 2; ks++) {
        const int grp = 2 * ks + subg;
        #pragma unroll
        for (int ma = 0; ma < 2; ma++) {
            int row = wy * 32 + ma * 16 + lrow + subh * 8;
            offA[ks][ma] = (uint32_t)(row * 64) +
                           ((uint32_t)(grp ^ ((row >> 1) & 3)) << 4);
        }
        #pragma unroll
        for (int nb = 0; nb < 4; nb++) {
            int row = wx * 64 + nb * 16 + lrow + subh * 8;
            offB[ks][nb] = 8192u + (uint32_t)(row * 64) +
                           ((uint32_t)(grp ^ ((row >> 1) & 3)) << 4);
        }
    }

    #pragma unroll
    for (int p = 0; p < 3; p++) {
        loadStage(p);
        CP_COMMIT();
    }

    #pragma unroll 1
    for (int s = 0; s < D / BK; s++) {
        CP_WAIT2();
        __syncthreads();
        if (s + 3 < D / BK) loadStage((s + 3) & 3);
        CP_COMMIT();

        const uint32_t base = sBase + (uint32_t)(s & 3) * STAGE_BYTES;
        #pragma unroll
        for (int ks = 0; ks < 2; ks++) {
            uint32_t a[2][4];
            #pragma unroll
            for (int ma = 0; ma < 2; ma++) ldsm4(a[ma], base + offA[ks][ma]);
            uint32_t bf[4][4];
            #pragma unroll
            for (int nb = 0; nb < 4; nb++) ldsm4(bf[nb], base + offB[ks][nb]);
            #pragma unroll
            for (int ma = 0; ma < 2; ma++)
                #pragma unroll
                for (int nb = 0; nb < 4; nb++) {
                    mma_fp8(acc[ma][2 * nb],     a[ma], bf[nb][0], bf[nb][2]);
                    mma_fp8(acc[ma][2 * nb + 1], a[ma], bf[nb][1], bf[nb][3]);
                }
        }
    }

    // epilogue: flag dot_fp8 > 0.5*(sq_i+sq_j) - 0.45 in permuted positions
    const bool diag = (ti == tj);
    const int g = lane >> 2, t4 = lane & 3;
    float hi[4];
    #pragma unroll
    for (int ma = 0; ma < 2; ma++)
        #pragma unroll
        for (int h = 0; h < 2; h++)
            hi[ma * 2 + h] = 0.5f * sqI[wy * 32 + ma * 16 + g + h * 8];
    float hj[16];
    #pragma unroll
    for (int nf = 0; nf < 8; nf++)
        #pragma unroll
        for (int bb = 0; bb < 2; bb++)
            hj[nf * 2 + bb] = thrJ[wx * 64 + nf * 8 + t4 * 2 + bb];

    #pragma unroll
    for (int ma = 0; ma < 2; ma++)
        #pragma unroll
        for (int nf = 0; nf < 8; nf++)
            #pragma unroll
            for (int r = 0; r < 4; r++) {
                float v = acc[ma][nf][r];
                float thr = hi[ma * 2 + (r >> 1)] + hj[nf * 2 + (r & 1)];
                if (v > thr) {
                    int pi = iBase + wy * 32 + ma * 16 + g + (r >> 1) * 8;
                    int pj = jBase + wx * 64 + nf * 8 + t4 * 2 + (r & 1);
                    if (!diag || pj > pi) {
                        unsigned pos = atomicAdd(&g_cand_n, 1u);
                        if (pos < CAP)
                            g_cand[pos] = ((unsigned)pi << 14) | (unsigned)pj;
                    }
                }
            }
}

// ---------------- kernel 4: exact fp32 fixup ----------------
__global__ void fixup_kernel(const float* __restrict__ classes,
                             const int* __restrict__ ids,
                             const float* __restrict__ emb) {
    unsigned n = g_cand_n;
    if (n > CAP) n = CAP;
    int warpId = (blockIdx.x * blockDim.x + threadIdx.x) >> 5;
    int lane = threadIdx.x & 31;
    int nWarps = (gridDim.x * blockDim.x) >> 5;
    for (unsigned c = warpId; c < n; c += nWarps) {
        unsigned pk = g_cand[c];
        int pi = pk >> 14, pj = pk & 16383;
        int i = g_perm[pi], j = g_perm[pj];
        if (i < 0 || j < 0) continue;
        float inv_i = g_inv[i], inv_j = g_inv[j];
        float s = 0.0f;
        #pragma unroll 4
        for (int k = lane; k < D; k += 32) {
            float a = emb[(size_t)i * D + k] * inv_i;
            float b = emb[(size_t)j * D + k] * inv_j;
            s += a * b;
        }
        #pragma unroll
        for (int o = 16; o > 0; o >>= 1) s += __shfl_down_sync(0xffffffff, s, o);
        if (lane == 0) {
            if (ids[i] != ids[j] && classes[i] == classes[j]) {
                float d2 = fmaxf(g_sq[i] + g_sq[j] - 2.0f * s, 0.0f);
                float term = fmaxf(0.0f, MARGIN - d2);
                if (term > 0.0f) atomicAdd(&g_hinge, term);
            }
        }
    }
}

// ---------------- kernel 5: BCE + final deterministic reduce ----------------
__global__ void final_kernel(const float* __restrict__ outputs,
                             const float* __restrict__ classes,
                             float* __restrict__ out) {
    int t = threadIdx.x;  // 256
    __shared__ float redP[256], redB[256];
    float sp = 0.0f;
    for (int i = t; i < NUM_IDS; i += 256) sp += g_pull[i];
    float sb = 0.0f;
    #pragma unroll
    for (int it = 0; it < B / 256; it++) {
        int i = t + it * 256;
        float o = outputs[i], cl = classes[i];
        sb += fmaxf(o, 0.0f) - o * cl + log1pf(expf(-fabsf(o)));
    }
    redP[t] = sp; redB[t] = sb;
    __syncthreads();
    #pragma unroll
    for (int k = 128; k > 0; k >>= 1) {
        if (t < k) { redP[t] += redP[t + k]; redB[t] += redB[t + k]; }
        __syncthreads();
    }
    if (t == 0) {
        float l = 0.5f * redP[0] + g_hinge;
        out[0] = redB[0] / (float)B + ALPHA * l;
    }
}

// ---------------------------------------------------------------------------
extern "C" void kernel_launch(void* const* d_in, const int* in_sizes, int n_in,
                              void* d_out, int out_size) {
    const float* outputs = (const float*)d_in[0];
    const float* classes = (const float*)d_in[1];
    const float* emb     = (const float*)d_in[2];
    const int*   ids     = (const int*)d_in[3];
    float* out = (float*)d_out;

    static cudaStream_t s1 = nullptr;
    static cudaEvent_t evA = nullptr, evB = nullptr;
    if (s1 == nullptr) {
        cudaStreamCreateWithFlags(&s1, cudaStreamNonBlocking);
        cudaEventCreateWithFlags(&evA, cudaEventDisableTiming);
        cudaEventCreateWithFlags(&evB, cudaEventDisableTiming);
        cudaFuncSetAttribute(gram_kernel,
                             cudaFuncAttributeMaxDynamicSharedMemorySize,
                             SMEM_GRAM);
    }

    partition_kernel<<<1, 1024>>>(classes);
    normalize_kernel<<<B, 128>>>(emb);
    // fork: pull on s1 runs concurrent with gram on the main stream
    cudaEventRecord(evA, 0);
    cudaStreamWaitEvent(s1, evA, 0);
    pull_kernel<<<NUM_IDS, 256, 0, s1>>>(classes, ids, emb);
    cudaEventRecord(evB, s1);

    gram_kernel<<<dim3(TRI_MAX, 2), 256, SMEM_GRAM>>>();
    fixup_kernel<<<64, 256>>>(classes, ids, emb);
    // join: final needs pull results
    cudaStreamWaitEvent(0, evB, 0);
    final_kernel<<<1, 256>>>(outputs, classes, out);
}